// round 16
// baseline (speedup 1.0000x reference)
#include <cuda_runtime.h>
#include <cuda_bf16.h>
#include <cstdint>
#include <math.h>

// ---------------------------------------------------------------------------
// Problem constants
// ---------------------------------------------------------------------------
#define B_ROWS   8192
#define M_EXP    10
#define N_TASK   100
#define F_CONN   10
#define T_OUT    10
#define K_IN     4096
#define H1_DIM   120

#define E1_BK    32
#define E1_NC    (K_IN / E1_BK)     // 128 chunks
#define PK_COLS  40                 // 32 data bf16 + 8 pad -> 80B rows
#define NTILES   (B_ROWS / 128)     // 64

// ---------------------------------------------------------------------------
// Scratch (device globals)
// ---------------------------------------------------------------------------
__device__ float g_EO[(size_t)M_EXP * B_ROWS * 10];
__device__ int   g_ready[NTILES];   // per-row-tile expert completion counters

__device__ __align__(16) __nv_bfloat16 g_xph[(size_t)E1_NC * B_ROWS * PK_COLS];
__device__ __align__(16) __nv_bfloat16 g_xpl[(size_t)E1_NC * B_ROWS * PK_COLS];
__device__ __align__(16) __nv_bfloat16 g_wph[(size_t)M_EXP * E1_NC * 128 * PK_COLS];
__device__ __align__(16) __nv_bfloat16 g_wpl[(size_t)M_EXP * E1_NC * 128 * PK_COLS];

__device__ __align__(16) __nv_bfloat16 g_w2h[(size_t)M_EXP * 4 * 96 * PK_COLS];
__device__ __align__(16) __nv_bfloat16 g_w2l[(size_t)M_EXP * 4 * 96 * PK_COLS];
__device__ __align__(16) __nv_bfloat16 g_tw2h[(size_t)N_TASK * 4 * 96 * PK_COLS];
__device__ __align__(16) __nv_bfloat16 g_tw2l[(size_t)N_TASK * 4 * 96 * PK_COLS];

// ---------------------------------------------------------------------------
// f32x2 helpers
// ---------------------------------------------------------------------------
__device__ __forceinline__ void fma2(unsigned long long& d,
                                     unsigned long long a,
                                     unsigned long long b) {
    asm("fma.rn.f32x2 %0, %1, %2, %0;" : "+l"(d) : "l"(a), "l"(b));
}
__device__ __forceinline__ unsigned long long dup2(float x) {
    unsigned long long r;
    unsigned int xi = __float_as_uint(x);
    asm("mov.b64 %0, {%1, %1};" : "=l"(r) : "r"(xi));
    return r;
}
__device__ __forceinline__ unsigned long long pack2(float lo, float hi) {
    unsigned long long r;
    asm("mov.b64 %0, {%1, %2};" : "=l"(r)
        : "r"(__float_as_uint(lo)), "r"(__float_as_uint(hi)));
    return r;
}
__device__ __forceinline__ void unpack2(unsigned long long v, float& lo, float& hi) {
    unsigned int a, b;
    asm("mov.b64 {%0, %1}, %2;" : "=r"(a), "=r"(b) : "l"(v));
    lo = __uint_as_float(a);
    hi = __uint_as_float(b);
}

// ---------------------------------------------------------------------------
// PTX helpers (<= sm_90 baseline; legal at virtual arch compute_103)
// ---------------------------------------------------------------------------
__device__ __forceinline__ uint32_t smem_u32(const void* p) {
    uint32_t a;
    asm("{ .reg .u64 t; cvta.to.shared.u64 t, %1; cvt.u32.u64 %0, t; }"
        : "=r"(a) : "l"(p));
    return a;
}
__device__ __forceinline__ void mbar_init(uint32_t mb, uint32_t cnt) {
    asm volatile("mbarrier.init.shared.b64 [%0], %1;" :: "r"(mb), "r"(cnt) : "memory");
}
__device__ __forceinline__ void mbar_expect_tx(uint32_t mb, uint32_t bytes) {
    asm volatile("mbarrier.arrive.expect_tx.shared.b64 _, [%0], %1;"
                 :: "r"(mb), "r"(bytes) : "memory");
}
__device__ __forceinline__ void mbar_wait(uint32_t mb, uint32_t parity) {
    asm volatile("{\n\t.reg .pred P;\n"
                 "W%=:\n\t"
                 "mbarrier.try_wait.parity.acquire.cta.shared::cta.b64 P, [%0], %1, 0x989680;\n\t"
                 "@P bra D%=;\n\t"
                 "bra W%=;\n"
                 "D%=:\n\t}"
                 :: "r"(mb), "r"(parity) : "memory");
}
__device__ __forceinline__ void bulk_g2s(uint32_t dst, const void* src,
                                         uint32_t bytes, uint32_t mb) {
    asm volatile("cp.async.bulk.shared::cta.global.mbarrier::complete_tx::bytes "
                 "[%0], [%1], %2, [%3];"
                 :: "r"(dst), "l"(src), "r"(bytes), "r"(mb) : "memory");
}
__device__ __forceinline__ void ldsm_x4(uint32_t& r0, uint32_t& r1,
                                        uint32_t& r2, uint32_t& r3, uint32_t a) {
    asm volatile("ldmatrix.sync.aligned.m8n8.x4.shared.b16 {%0,%1,%2,%3}, [%4];"
                 : "=r"(r0), "=r"(r1), "=r"(r2), "=r"(r3) : "r"(a));
}
__device__ __forceinline__ void mma_bf16(float& c0, float& c1, float& c2, float& c3,
                                         uint32_t a0, uint32_t a1, uint32_t a2, uint32_t a3,
                                         uint32_t b0, uint32_t b1) {
    asm volatile("mma.sync.aligned.m16n8k16.row.col.f32.bf16.bf16.f32 "
                 "{%0,%1,%2,%3},{%4,%5,%6,%7},{%8,%9},{%0,%1,%2,%3};"
                 : "+f"(c0), "+f"(c1), "+f"(c2), "+f"(c3)
                 : "r"(a0), "r"(a1), "r"(a2), "r"(a3), "r"(b0), "r"(b1));
}

// ---------------------------------------------------------------------------
// Vectorized merged packing kernel (+ folded flag reset in block 0)
// ---------------------------------------------------------------------------
#define PX_G  ((size_t)E1_NC * B_ROWS * 5)
#define PW_G  ((size_t)M_EXP * E1_NC * 128 * 5)
#define P2E_G ((size_t)M_EXP * 4 * 96 * 5)
#define P2T_G ((size_t)N_TASK * 4 * 96 * 5)
#define PACK_G_TOTAL (PX_G + PW_G + P2E_G + P2T_G)

__device__ __forceinline__ uint32_t bf2u(float a, float b) {
    __nv_bfloat162 t;
    t.x = __float2bfloat16(a);
    t.y = __float2bfloat16(b);
    return *reinterpret_cast<uint32_t*>(&t);
}

__device__ __forceinline__ void split8_store(const float* f,
                                             __nv_bfloat16* __restrict__ ph,
                                             __nv_bfloat16* __restrict__ pl,
                                             size_t g8)
{
    float l[8];
    #pragma unroll
    for (int j = 0; j < 8; j++) {
        __nv_bfloat16 hb = __float2bfloat16(f[j]);
        l[j] = f[j] - __bfloat162float(hb);
    }
    uint4 H, L;
    H.x = bf2u(f[0] - l[0], f[1] - l[1]);
    H.y = bf2u(f[2] - l[2], f[3] - l[3]);
    H.z = bf2u(f[4] - l[4], f[5] - l[5]);
    H.w = bf2u(f[6] - l[6], f[7] - l[7]);
    L.x = bf2u(l[0], l[1]);
    L.y = bf2u(l[2], l[3]);
    L.z = bf2u(l[4], l[5]);
    L.w = bf2u(l[6], l[7]);
    *reinterpret_cast<uint4*>(ph + g8 * 8) = H;
    *reinterpret_cast<uint4*>(pl + g8 * 8) = L;
}

__global__ void pack_all_kernel(const float* __restrict__ x,
                                const float* __restrict__ eW1,
                                const float* __restrict__ eW2,
                                const float* __restrict__ tW2,
                                __nv_bfloat16* __restrict__ xph,
                                __nv_bfloat16* __restrict__ xpl,
                                __nv_bfloat16* __restrict__ wph,
                                __nv_bfloat16* __restrict__ wpl,
                                __nv_bfloat16* __restrict__ w2h,
                                __nv_bfloat16* __restrict__ w2l,
                                __nv_bfloat16* __restrict__ tw2h,
                                __nv_bfloat16* __restrict__ tw2l)
{
    // folded ready-flag reset (pack completes before fused_kernel launches,
    // so stream order guarantees visibility)
    if (blockIdx.x == 0 && threadIdx.x < NTILES)
        g_ready[threadIdx.x] = 0;

    size_t gi = (size_t)blockIdx.x * blockDim.x + threadIdx.x;
    if (gi >= PACK_G_TOTAL) return;

    float f[8];
    #pragma unroll
    for (int j = 0; j < 8; j++) f[j] = 0.f;

    if (gi < PX_G) {
        size_t i = gi;
        int g = (int)(i % 5);
        size_t rc = i / 5;
        int row = (int)(rc % B_ROWS);
        int c   = (int)(rc / B_ROWS);
        if (g < 4) {
            const float* src = x + (size_t)row * K_IN + c * E1_BK + g * 8;
            float4 a = *reinterpret_cast<const float4*>(src);
            float4 b = *reinterpret_cast<const float4*>(src + 4);
            f[0] = a.x; f[1] = a.y; f[2] = a.z; f[3] = a.w;
            f[4] = b.x; f[5] = b.y; f[6] = b.z; f[7] = b.w;
        }
        split8_store(f, xph, xpl, i);
    } else if (gi < PX_G + PW_G) {
        size_t i = gi - PX_G;
        int g = (int)(i % 5);
        int n = (int)((i / 5) % 128);
        int c = (int)((i / (5 * 128)) % E1_NC);
        int m = (int)(i / ((size_t)5 * 128 * E1_NC));
        if (g < 4 && n < H1_DIM) {
            #pragma unroll
            for (int j = 0; j < 8; j++) {
                int k = c * E1_BK + g * 8 + j;
                f[j] = eW1[((size_t)m * K_IN + k) * H1_DIM + n];
            }
        }
        split8_store(f, wph, wpl, i);
    } else if (gi < PX_G + PW_G + P2E_G) {
        size_t i = gi - PX_G - PW_G;
        int g = (int)(i % 5);
        int n = (int)((i / 5) % 96);
        int c = (int)((i / (5 * 96)) % 4);
        int b = (int)(i / ((size_t)5 * 96 * 4));
        if (g < 4 && n < 84) {
            #pragma unroll
            for (int j = 0; j < 8; j++) {
                int k = c * 32 + g * 8 + j;
                if (k < 120) f[j] = eW2[((size_t)b * 120 + k) * 84 + n];
            }
        }
        split8_store(f, w2h, w2l, i);
    } else {
        size_t i = gi - PX_G - PW_G - P2E_G;
        int g = (int)(i % 5);
        int n = (int)((i / 5) % 96);
        int c = (int)((i / (5 * 96)) % 4);
        int b = (int)(i / ((size_t)5 * 96 * 4));
        if (g < 4 && n < 84) {
            #pragma unroll
            for (int j = 0; j < 8; j++) {
                int k = c * 32 + g * 8 + j;
                if (k < 120) f[j] = tW2[((size_t)b * 120 + k) * 84 + n];
            }
        }
        split8_store(f, tw2h, tw2l, i);
    }
}

// ---------------------------------------------------------------------------
// fused kernel: blocks [0,640) = expert (m = bx%10, tileY = bx/10)
//               blocks [640, 7040) = task (tileY = j/100 slow, n = j%100)
// Task CTAs spin on g_ready[tileY] == 10 before reading EO.
// smem 110,592 B -> 2 CTAs/SM for both roles.  256 threads.
// ---------------------------------------------------------------------------
#define RS          80
#define STG_SZ      40960
#define XA_H        0
#define XA_L        10240
#define XB_H        20480
#define XB_L        30720
#define EB_H        81920
#define EB_L        89600
#define EW3S        97280
#define EMB         100640
#define MSTR        90

#define TK_AH      0
#define TK_AL      40960
#define TB_H       81920
#define TB_L       89600
#define TK_GS      97280
#define TK_W1      102400
#define TK_W3      107200
#define TK_MB      110560
#define FK_SMEM    110592

__global__ __launch_bounds__(256, 2)
void fused_kernel(const __nv_bfloat16* __restrict__ xph,
                  const __nv_bfloat16* __restrict__ xpl,
                  const __nv_bfloat16* __restrict__ wph,
                  const __nv_bfloat16* __restrict__ wpl,
                  const float* __restrict__ eb1,
                  const __nv_bfloat16* __restrict__ w2h,
                  const __nv_bfloat16* __restrict__ w2l,
                  const float* __restrict__ eb2,
                  const float* __restrict__ eW3,
                  const float* __restrict__ eb3,
                  const float* __restrict__ gw,
                  const int*   __restrict__ gm,
                  const float* __restrict__ tW1,
                  const float* __restrict__ tb1,
                  const __nv_bfloat16* __restrict__ tw2h,
                  const __nv_bfloat16* __restrict__ tw2l,
                  const float* __restrict__ tb2,
                  const float* __restrict__ tW3,
                  const float* __restrict__ tb3,
                  const float* __restrict__ gl,
                  float* __restrict__ EO,
                  float* __restrict__ Out,
                  float* __restrict__ Loss)
{
    extern __shared__ char smem[];
    const uint32_t sb = smem_u32(smem);
    const int t    = threadIdx.x;
    const int lane = t & 31;
    const int wid  = t >> 5;
    const int wm   = wid >> 1;
    const int wn   = wid & 1;
    const int bx   = blockIdx.x;

    if (bx < M_EXP * NTILES) {
        // =================== EXPERT ROLE ===================
        const int m     = bx % M_EXP;
        const int tileY = bx / M_EXP;
        const int r0    = tileY * 128;

        const uint32_t mb = sb + EMB;

        if (t == 0) {
            mbar_init(mb + 0, 1);
            mbar_init(mb + 8, 1);
            mbar_init(mb + 16, 1);
        }
        __syncthreads();

        auto issue_e1 = [&](int c, int s) {
            mbar_expect_tx(mb + 8 * s, 4 * 10240);
            const uint32_t stg = sb + s * STG_SZ;
            const size_t aoff = ((size_t)c * B_ROWS + (size_t)tileY * 128) * PK_COLS;
            const size_t boff = ((size_t)m * E1_NC + c) * 128 * PK_COLS;
            bulk_g2s(stg + XA_H, xph + aoff, 10240, mb + 8 * s);
            bulk_g2s(stg + XA_L, xpl + aoff, 10240, mb + 8 * s);
            bulk_g2s(stg + XB_H, wph + boff, 10240, mb + 8 * s);
            bulk_g2s(stg + XB_L, wpl + boff, 10240, mb + 8 * s);
        };

        if (t == 0) {
            mbar_expect_tx(mb + 16, 2 * 7680);
            bulk_g2s(sb + EB_H, w2h + (size_t)m * 4 * 3840, 7680, mb + 16);
            bulk_g2s(sb + EB_L, w2l + (size_t)m * 4 * 3840, 7680, mb + 16);
            issue_e1(0, 0);
        }

        // -------- E1 --------
        float acc[2][8][4];
        #pragma unroll
        for (int i = 0; i < 2; i++)
            #pragma unroll
            for (int j = 0; j < 8; j++)
                #pragma unroll
                for (int q = 0; q < 4; q++)
                    acc[i][j][q] = 0.f;

        const uint32_t a_base = (uint32_t)((wm * 32 + (lane & 15)) * RS + (lane >> 4) * 16);
        const uint32_t b_base = (uint32_t)((wn * 64 + (lane & 15)) * RS + (lane >> 4) * 16);

        uint32_t ph[2] = {0u, 0u};

        for (int c = 0; c < E1_NC; c++) {
            const int s = c & 1;
            if (c + 1 < E1_NC && t == 0) issue_e1(c + 1, s ^ 1);
            mbar_wait(mb + 8 * s, ph[s]);
            ph[s] ^= 1u;

            const uint32_t stg = sb + s * STG_SZ;
            #pragma unroll
            for (int ks = 0; ks < 2; ks++) {
                const uint32_t ko = ks * 32;
                uint32_t ah[2][4], al[2][4];
                #pragma unroll
                for (int mt = 0; mt < 2; mt++) {
                    uint32_t ad = stg + a_base + mt * (16 * RS) + ko;
                    ldsm_x4(ah[mt][0], ah[mt][1], ah[mt][2], ah[mt][3], ad + XA_H);
                    ldsm_x4(al[mt][0], al[mt][1], al[mt][2], al[mt][3], ad + XA_L);
                }
                uint32_t bh[4][4], bl[4][4];
                #pragma unroll
                for (int g = 0; g < 4; g++) {
                    uint32_t bd = stg + b_base + g * (16 * RS) + ko;
                    ldsm_x4(bh[g][0], bh[g][1], bh[g][2], bh[g][3], bd + XB_H);
                    ldsm_x4(bl[g][0], bl[g][1], bl[g][2], bl[g][3], bd + XB_L);
                }
                #pragma unroll
                for (int mt = 0; mt < 2; mt++) {
                    #pragma unroll
                    for (int nt = 0; nt < 8; nt++) {
                        const int g = nt >> 1, p = (nt & 1);
                        float* cc = acc[mt][nt];
                        mma_bf16(cc[0], cc[1], cc[2], cc[3],
                                 ah[mt][0], ah[mt][1], ah[mt][2], ah[mt][3],
                                 bh[g][p], bh[g][p + 2]);
                        mma_bf16(cc[0], cc[1], cc[2], cc[3],
                                 ah[mt][0], ah[mt][1], ah[mt][2], ah[mt][3],
                                 bl[g][p], bl[g][p + 2]);
                        mma_bf16(cc[0], cc[1], cc[2], cc[3],
                                 al[mt][0], al[mt][1], al[mt][2], al[mt][3],
                                 bh[g][p], bh[g][p + 2]);
                    }
                }
            }
            __syncthreads();
        }

        // -------- H1 tile -> smem (relu+bias, split hi/lo) --------
        {
            const float* bias = eb1 + (size_t)m * H1_DIM;
            const int rl = wm * 32 + (lane >> 2);
            const int cb = wn * 64 + (lane & 3) * 2;
            #pragma unroll
            for (int mt = 0; mt < 2; mt++) {
                #pragma unroll
                for (int half = 0; half < 2; half++) {
                    const int r = rl + mt * 16 + half * 8;
                    #pragma unroll
                    for (int nt = 0; nt < 8; nt++) {
                        const int ccol = cb + nt * 8;
                        if (ccol < H1_DIM) {
                            float v0 = fmaxf(acc[mt][nt][half * 2 + 0] + bias[ccol], 0.f);
                            float v1 = fmaxf(acc[mt][nt][half * 2 + 1] + bias[ccol + 1], 0.f);
                            __nv_bfloat16 h0 = __float2bfloat16(v0);
                            __nv_bfloat16 h1 = __float2bfloat16(v1);
                            __nv_bfloat162 hh; hh.x = h0; hh.y = h1;
                            __nv_bfloat162 ll;
                            ll.x = __float2bfloat16(v0 - __bfloat162float(h0));
                            ll.y = __float2bfloat16(v1 - __bfloat162float(h1));
                            uint32_t off = (ccol >> 5) * 10240 + r * RS + (ccol & 31) * 2;
                            *reinterpret_cast<__nv_bfloat162*>(smem + 0     + off) = hh;
                            *reinterpret_cast<__nv_bfloat162*>(smem + 40960 + off) = ll;
                        }
                    }
                }
            }
            if (t < 128) {
                uint32_t off = 3 * 10240 + t * RS + 48;
                *reinterpret_cast<uint4*>(smem + 0     + off) = make_uint4(0u,0u,0u,0u);
                *reinterpret_cast<uint4*>(smem + 40960 + off) = make_uint4(0u,0u,0u,0u);
            }
            float* w3s = reinterpret_cast<float*>(smem + EW3S);
            const float* w3g = eW3 + (size_t)m * (84 * T_OUT);
            for (int i = t; i < 84 * T_OUT; i += 256) w3s[i] = w3g[i];
        }
        __syncthreads();

        // -------- E2 MMA (B streamed per chunk) --------
        float acc2[2][6][4];
        #pragma unroll
        for (int i = 0; i < 2; i++)
            #pragma unroll
            for (int j = 0; j < 6; j++)
                #pragma unroll
                for (int q = 0; q < 4; q++)
                    acc2[i][j][q] = 0.f;

        const uint32_t b2_base = (uint32_t)((wn * 48 + (lane & 15)) * RS + (lane >> 4) * 16);
        uint32_t phb = 0u;
        #pragma unroll
        for (int ch = 0; ch < 4; ch++) {
            mbar_wait(mb + 16, phb);
            phb ^= 1u;
            #pragma unroll
            for (int ks = 0; ks < 2; ks++) {
                const uint32_t ko = ks * 32;
                uint32_t ah[2][4], al[2][4];
                #pragma unroll
                for (int mt = 0; mt < 2; mt++) {
                    uint32_t ad = sb + ch * 10240 + a_base + mt * (16 * RS) + ko;
                    ldsm_x4(ah[mt][0], ah[mt][1], ah[mt][2], ah[mt][3], ad + 0);
                    ldsm_x4(al[mt][0], al[mt][1], al[mt][2], al[mt][3], ad + 40960);
                }
                uint32_t bh[3][4], bl[3][4];
                #pragma unroll
                for (int g = 0; g < 3; g++) {
                    uint32_t bd = sb + b2_base + g * (16 * RS) + ko;
                    ldsm_x4(bh[g][0], bh[g][1], bh[g][2], bh[g][3], bd + EB_H);
                    ldsm_x4(bl[g][0], bl[g][1], bl[g][2], bl[g][3], bd + EB_L);
                }
                #pragma unroll
                for (int mt = 0; mt < 2; mt++) {
                    #pragma unroll
                    for (int nt = 0; nt < 6; nt++) {
                        const int g = nt >> 1, p = (nt & 1);
                        float* cc = acc2[mt][nt];
                        mma_bf16(cc[0], cc[1], cc[2], cc[3],
                                 ah[mt][0], ah[mt][1], ah[mt][2], ah[mt][3],
                                 bh[g][p], bh[g][p + 2]);
                        mma_bf16(cc[0], cc[1], cc[2], cc[3],
                                 ah[mt][0], ah[mt][1], ah[mt][2], ah[mt][3],
                                 bl[g][p], bl[g][p + 2]);
                        mma_bf16(cc[0], cc[1], cc[2], cc[3],
                                 al[mt][0], al[mt][1], al[mt][2], al[mt][3],
                                 bh[g][p], bh[g][p + 2]);
                    }
                }
            }
            __syncthreads();
            if (ch < 3 && t == 0) {
                mbar_expect_tx(mb + 16, 2 * 7680);
                bulk_g2s(sb + EB_H, w2h + ((size_t)m * 4 + ch + 1) * 3840, 7680, mb + 16);
                bulk_g2s(sb + EB_L, w2l + ((size_t)m * 4 + ch + 1) * 3840, 7680, mb + 16);
            }
        }

        // -------- E3 epilogue --------
        float* mids = reinterpret_cast<float*>(smem);
        float* w3s  = reinterpret_cast<float*>(smem + EW3S);
        {
            const float* b2 = eb2 + (size_t)m * 84;
            const int rl = wm * 32 + (lane >> 2);
            const int cb = wn * 48 + (lane & 3) * 2;
            #pragma unroll
            for (int mt = 0; mt < 2; mt++) {
                #pragma unroll
                for (int half = 0; half < 2; half++) {
                    const int r = rl + mt * 16 + half * 8;
                    float* row = mids + r * MSTR;
                    #pragma unroll
                    for (int nt = 0; nt < 6; nt++) {
                        const int ccol = cb + nt * 8;
                        if (ccol < 84) {
                            float2 v;
                            v.x = fmaxf(acc2[mt][nt][half * 2 + 0] + b2[ccol], 0.f);
                            v.y = fmaxf(acc2[mt][nt][half * 2 + 1] + b2[ccol + 1], 0.f);
                            *reinterpret_cast<float2*>(row + ccol) = v;
                        }
                    }
                }
            }
        }
        __syncthreads();
        {
            const int r  = t >> 1;
            const int c0 = (t & 1) * 5;
            const float* b3 = eb3 + (size_t)m * T_OUT;
            float a[5];
            #pragma unroll
            for (int j = 0; j < 5; j++) a[j] = b3[c0 + j];
            const float* row = mids + r * MSTR;
            for (int k = 0; k < 84; k++) {
                float tv = row[k];
                #pragma unroll
                for (int j = 0; j < 5; j++)
                    a[j] = fmaf(tv, w3s[k * T_OUT + c0 + j], a[j]);
            }
            float* dst = EO + ((size_t)m * B_ROWS + r0 + r) * T_OUT + c0;
            #pragma unroll
            for (int j = 0; j < 5; j++) dst[j] = a[j];
        }
        // publish tile completion
        __syncthreads();
        if (t == 0) {
            __threadfence();
            atomicAdd(&g_ready[tileY], 1);
        }
    } else {
        // =================== TASK ROLE ===================
        const int j2    = bx - M_EXP * NTILES;
        const int tileY = j2 / N_TASK;        // slow: early tasks wait on early tiles
        const int n     = j2 % N_TASK;
        const int r0    = tileY * 128;

        const uint32_t mb = sb + TK_MB;
        if (t == 0) mbar_init(mb, 1);
        __syncthreads();
        if (t == 0) {
            mbar_expect_tx(mb, 2 * 7680);
            bulk_g2s(sb + TB_H, tw2h + (size_t)n * 4 * 3840, 7680, mb);
            bulk_g2s(sb + TB_L, tw2l + (size_t)n * 4 * 3840, 7680, mb);
        }

        if (tileY == 0 && t == 32) {
            float acc = 0.f;
            #pragma unroll
            for (int m = 0; m < M_EXP; m++) {
                float v = gl[m * N_TASK + n];
                float ls = (v > 0.f) ? (-log1pf(expf(-v))) : (v - log1pf(expf(v)));
                acc += ls;
            }
            Loss[n] = acc;
        }

        float* Gs  = reinterpret_cast<float*>(smem + TK_GS);
        float* W1s = reinterpret_cast<float*>(smem + TK_W1);
        float* w3s = reinterpret_cast<float*>(smem + TK_W3);

        // EO-independent smem loads first (overlap with spin)
        for (int i = t; i < F_CONN * 120; i += 256)
            W1s[i] = tW1[(size_t)n * F_CONN * 120 + i];
        for (int i = t; i < 84 * T_OUT; i += 256)
            w3s[i] = tW3[(size_t)n * 84 * T_OUT + i];

        // wait until all 10 experts for this row tile published
        if (t == 0) {
            while (atomicAdd(&g_ready[tileY], 0) < M_EXP) __nanosleep(64);
        }
        __syncthreads();

        float w[M_EXP];
        #pragma unroll
        for (int m = 0; m < M_EXP; m++)
            w[m] = gw[m * N_TASK + n] * (float)gm[m * N_TASK + n];

        // gate combine (L1-bypassing loads: EO written by other SMs this launch)
        for (int i = t; i < 128 * F_CONN; i += 256) {
            float acc = 0.f;
            #pragma unroll
            for (int m = 0; m < M_EXP; m++)
                acc = fmaf(w[m], __ldcg(&EO[((size_t)m * B_ROWS + r0) * F_CONN + i]), acc);
            Gs[i] = acc;
        }
        __syncthreads();

        // T1: thread = (row, 60-col half); relu'd hi/lo -> A tile
        {
            const int r  = t >> 1;
            const int h0 = (t & 1) * 60;
            float g[F_CONN];
            #pragma unroll
            for (int f = 0; f < F_CONN; f++) g[f] = Gs[r * F_CONN + f];

            unsigned long long a2[30];
            const float* b1 = tb1 + (size_t)n * 120 + h0;
            #pragma unroll
            for (int j = 0; j < 30; j++) a2[j] = pack2(b1[2 * j], b1[2 * j + 1]);
            #pragma unroll
            for (int f = 0; f < F_CONN; f++) {
                unsigned long long gv = dup2(g[f]);
                const unsigned long long* wrow =
                    reinterpret_cast<const unsigned long long*>(W1s + f * 120 + h0);
                #pragma unroll
                for (int j = 0; j < 30; j++) fma2(a2[j], gv, wrow[j]);
            }
            #pragma unroll
            for (int j = 0; j < 30; j++) {
                float v0, v1;
                unpack2(a2[j], v0, v1);
                v0 = fmaxf(v0, 0.f);
                v1 = fmaxf(v1, 0.f);
                __nv_bfloat16 h0b = __float2bfloat16(v0);
                __nv_bfloat16 h1b = __float2bfloat16(v1);
                __nv_bfloat162 hh; hh.x = h0b; hh.y = h1b;
                __nv_bfloat162 ll;
                ll.x = __float2bfloat16(v0 - __bfloat162float(h0b));
                ll.y = __float2bfloat16(v1 - __bfloat162float(h1b));
                const int c = h0 + 2 * j;
                uint32_t off = (c >> 5) * 10240 + r * RS + (c & 31) * 2;
                *reinterpret_cast<__nv_bfloat162*>(smem + TK_AH + off) = hh;
                *reinterpret_cast<__nv_bfloat162*>(smem + TK_AL + off) = ll;
            }
            if (t & 1) {
                uint32_t off = 3 * 10240 + r * RS + 48;
                *reinterpret_cast<uint4*>(smem + TK_AH + off) = make_uint4(0u,0u,0u,0u);
                *reinterpret_cast<uint4*>(smem + TK_AL + off) = make_uint4(0u,0u,0u,0u);
            }
        }
        __syncthreads();

        // T2 MMA (B streamed per chunk)
        float acc2[2][6][4];
        #pragma unroll
        for (int i = 0; i < 2; i++)
            #pragma unroll
            for (int j = 0; j < 6; j++)
                #pragma unroll
                for (int q = 0; q < 4; q++)
                    acc2[i][j][q] = 0.f;

        const uint32_t a_base  = (uint32_t)((wm * 32 + (lane & 15)) * RS + (lane >> 4) * 16);
        const uint32_t b2_base = (uint32_t)((wn * 48 + (lane & 15)) * RS + (lane >> 4) * 16);
        uint32_t phb = 0u;
        #pragma unroll
        for (int ch = 0; ch < 4; ch++) {
            mbar_wait(mb, phb);
            phb ^= 1u;
            #pragma unroll
            for (int ks = 0; ks < 2; ks++) {
                const uint32_t ko = ks * 32;
                uint32_t ah[2][4], al[2][4];
                #pragma unroll
                for (int mt = 0; mt < 2; mt++) {
                    uint32_t ad = sb + ch * 10240 + a_base + mt * (16 * RS) + ko;
                    ldsm_x4(ah[mt][0], ah[mt][1], ah[mt][2], ah[mt][3], ad + TK_AH);
                    ldsm_x4(al[mt][0], al[mt][1], al[mt][2], al[mt][3], ad + TK_AL);
                }
                uint32_t bh[3][4], bl[3][4];
                #pragma unroll
                for (int g = 0; g < 3; g++) {
                    uint32_t bd = sb + b2_base + g * (16 * RS) + ko;
                    ldsm_x4(bh[g][0], bh[g][1], bh[g][2], bh[g][3], bd + TB_H);
                    ldsm_x4(bl[g][0], bl[g][1], bl[g][2], bl[g][3], bd + TB_L);
                }
                #pragma unroll
                for (int mt = 0; mt < 2; mt++) {
                    #pragma unroll
                    for (int nt = 0; nt < 6; nt++) {
                        const int g = nt >> 1, p = (nt & 1);
                        float* cc = acc2[mt][nt];
                        mma_bf16(cc[0], cc[1], cc[2], cc[3],
                                 ah[mt][0], ah[mt][1], ah[mt][2], ah[mt][3],
                                 bh[g][p], bh[g][p + 2]);
                        mma_bf16(cc[0], cc[1], cc[2], cc[3],
                                 ah[mt][0], ah[mt][1], ah[mt][2], ah[mt][3],
                                 bl[g][p], bl[g][p + 2]);
                        mma_bf16(cc[0], cc[1], cc[2], cc[3],
                                 al[mt][0], al[mt][1], al[mt][2], al[mt][3],
                                 bh[g][p], bh[g][p + 2]);
                    }
                }
            }
            __syncthreads();
            if (ch < 3 && t == 0) {
                mbar_expect_tx(mb, 2 * 7680);
                bulk_g2s(sb + TB_H, tw2h + ((size_t)n * 4 + ch + 1) * 3840, 7680, mb);
                bulk_g2s(sb + TB_L, tw2l + ((size_t)n * 4 + ch + 1) * 3840, 7680, mb);
            }
        }

        // T3 epilogue
        float* mids = reinterpret_cast<float*>(smem);
        {
            const float* b2 = tb2 + (size_t)n * 84;
            const int rl = wm * 32 + (lane >> 2);
            const int cb = wn * 48 + (lane & 3) * 2;
            #pragma unroll
            for (int mt = 0; mt < 2; mt++) {
                #pragma unroll
                for (int half = 0; half < 2; half++) {
                    const int r = rl + mt * 16 + half * 8;
                    float* row = mids + r * MSTR;
                    #pragma unroll
                    for (int nt = 0; nt < 6; nt++) {
                        const int ccol = cb + nt * 8;
                        if (ccol < 84) {
                            float2 v;
                            v.x = fmaxf(acc2[mt][nt][half * 2 + 0] + b2[ccol], 0.f);
                            v.y = fmaxf(acc2[mt][nt][half * 2 + 1] + b2[ccol + 1], 0.f);
                            *reinterpret_cast<float2*>(row + ccol) = v;
                        }
                    }
                }
            }
        }
        __syncthreads();
        {
            const int r  = t >> 1;
            const int c0 = (t & 1) * 5;
            const float* b3 = tb3 + (size_t)n * T_OUT;
            float a[5];
            #pragma unroll
            for (int j = 0; j < 5; j++) a[j] = b3[c0 + j];
            const float* row = mids + r * MSTR;
            for (int k = 0; k < 84; k++) {
                float tv = row[k];
                #pragma unroll
                for (int j = 0; j < 5; j++)
                    a[j] = fmaf(tv, w3s[k * T_OUT + c0 + j], a[j]);
            }
            float* dst = Out + ((size_t)n * B_ROWS + r0 + r) * T_OUT + c0;
            #pragma unroll
            for (int j = 0; j < 5; j++) dst[j] = a[j];
        }
    }
}

// ---------------------------------------------------------------------------
// kernel_launch
// ---------------------------------------------------------------------------
extern "C" void kernel_launch(void* const* d_in, const int* in_sizes, int n_in,
                              void* d_out, int out_size)
{
    const float* x   = (const float*)d_in[0];
    const float* eW1 = (const float*)d_in[2];
    const float* eb1 = (const float*)d_in[3];
    const float* eW2 = (const float*)d_in[4];
    const float* eb2 = (const float*)d_in[5];
    const float* eW3 = (const float*)d_in[6];
    const float* eb3 = (const float*)d_in[7];
    const float* gw  = (const float*)d_in[8];
    const float* gl  = (const float*)d_in[9];
    const int*   gm  = (const int*)  d_in[10];
    const float* tW1 = (const float*)d_in[11];
    const float* tb1 = (const float*)d_in[12];
    const float* tW2 = (const float*)d_in[13];
    const float* tb2 = (const float*)d_in[14];
    const float* tW3 = (const float*)d_in[15];
    const float* tb3 = (const float*)d_in[16];
    float* out = (float*)d_out;

    float *EO;
    __nv_bfloat16 *xph, *xpl, *wph, *wpl, *w2h, *w2l, *tw2h, *tw2l;
    cudaGetSymbolAddress((void**)&EO,  g_EO);
    cudaGetSymbolAddress((void**)&xph, g_xph);
    cudaGetSymbolAddress((void**)&xpl, g_xpl);
    cudaGetSymbolAddress((void**)&wph, g_wph);
    cudaGetSymbolAddress((void**)&wpl, g_wpl);
    cudaGetSymbolAddress((void**)&w2h, g_w2h);
    cudaGetSymbolAddress((void**)&w2l, g_w2l);
    cudaGetSymbolAddress((void**)&tw2h, g_tw2h);
    cudaGetSymbolAddress((void**)&tw2l, g_tw2l);

    cudaFuncSetAttribute(fused_kernel,
                         cudaFuncAttributeMaxDynamicSharedMemorySize, FK_SMEM);

    // vectorized merged packing (one launch; also resets ready flags)
    {
        unsigned blocks = (unsigned)((PACK_G_TOTAL + 255) / 256);
        pack_all_kernel<<<blocks, 256>>>(x, eW1, eW2, tW2,
                                         xph, xpl, wph, wpl,
                                         w2h, w2l, tw2h, tw2l);
    }

    // fused expert+task with flag-based cross-phase overlap
    fused_kernel<<<(M_EXP + N_TASK) * NTILES, 256, FK_SMEM>>>(
        xph, xpl, wph, wpl, eb1, w2h, w2l, eb2, eW3, eb3,
        gw, gm, tW1, tb1, tw2h, tw2l, tb2, tW3, tb3, gl,
        EO, out, out + (long long)N_TASK * B_ROWS * T_OUT);
}

// round 17
// speedup vs baseline: 1.0031x; 1.0031x over previous
#include <cuda_runtime.h>
#include <cuda_bf16.h>
#include <cstdint>
#include <math.h>

// ---------------------------------------------------------------------------
// Problem constants
// ---------------------------------------------------------------------------
#define B_ROWS   8192
#define M_EXP    10
#define N_TASK   100
#define F_CONN   10
#define T_OUT    10
#define K_IN     4096
#define H1_DIM   120

#define E1_BK    32
#define E1_NC    (K_IN / E1_BK)     // 128 chunks
#define PK_COLS  40                 // 32 data bf16 + 8 pad -> 80B rows
#define NTILES   (B_ROWS / 128)     // 64

// ---------------------------------------------------------------------------
// Scratch (device globals)
// ---------------------------------------------------------------------------
__device__ float g_EO[(size_t)M_EXP * B_ROWS * 10];
__device__ int   g_ready[NTILES];   // per-row-tile expert completion counters

__device__ __align__(16) __nv_bfloat16 g_xph[(size_t)E1_NC * B_ROWS * PK_COLS];
__device__ __align__(16) __nv_bfloat16 g_xpl[(size_t)E1_NC * B_ROWS * PK_COLS];
__device__ __align__(16) __nv_bfloat16 g_wph[(size_t)M_EXP * E1_NC * 128 * PK_COLS];
__device__ __align__(16) __nv_bfloat16 g_wpl[(size_t)M_EXP * E1_NC * 128 * PK_COLS];

__device__ __align__(16) __nv_bfloat16 g_w2h[(size_t)M_EXP * 4 * 96 * PK_COLS];
__device__ __align__(16) __nv_bfloat16 g_w2l[(size_t)M_EXP * 4 * 96 * PK_COLS];
__device__ __align__(16) __nv_bfloat16 g_tw2h[(size_t)N_TASK * 4 * 96 * PK_COLS];
__device__ __align__(16) __nv_bfloat16 g_tw2l[(size_t)N_TASK * 4 * 96 * PK_COLS];

// ---------------------------------------------------------------------------
// f32x2 helpers
// ---------------------------------------------------------------------------
__device__ __forceinline__ void fma2(unsigned long long& d,
                                     unsigned long long a,
                                     unsigned long long b) {
    asm("fma.rn.f32x2 %0, %1, %2, %0;" : "+l"(d) : "l"(a), "l"(b));
}
__device__ __forceinline__ unsigned long long dup2(float x) {
    unsigned long long r;
    unsigned int xi = __float_as_uint(x);
    asm("mov.b64 %0, {%1, %1};" : "=l"(r) : "r"(xi));
    return r;
}
__device__ __forceinline__ unsigned long long pack2(float lo, float hi) {
    unsigned long long r;
    asm("mov.b64 %0, {%1, %2};" : "=l"(r)
        : "r"(__float_as_uint(lo)), "r"(__float_as_uint(hi)));
    return r;
}
__device__ __forceinline__ void unpack2(unsigned long long v, float& lo, float& hi) {
    unsigned int a, b;
    asm("mov.b64 {%0, %1}, %2;" : "=r"(a), "=r"(b) : "l"(v));
    lo = __uint_as_float(a);
    hi = __uint_as_float(b);
}

// ---------------------------------------------------------------------------
// PTX helpers (<= sm_90 baseline; legal at virtual arch compute_103)
// ---------------------------------------------------------------------------
__device__ __forceinline__ uint32_t smem_u32(const void* p) {
    uint32_t a;
    asm("{ .reg .u64 t; cvta.to.shared.u64 t, %1; cvt.u32.u64 %0, t; }"
        : "=r"(a) : "l"(p));
    return a;
}
__device__ __forceinline__ void mbar_init(uint32_t mb, uint32_t cnt) {
    asm volatile("mbarrier.init.shared.b64 [%0], %1;" :: "r"(mb), "r"(cnt) : "memory");
}
__device__ __forceinline__ void mbar_expect_tx(uint32_t mb, uint32_t bytes) {
    asm volatile("mbarrier.arrive.expect_tx.shared.b64 _, [%0], %1;"
                 :: "r"(mb), "r"(bytes) : "memory");
}
__device__ __forceinline__ void mbar_wait(uint32_t mb, uint32_t parity) {
    asm volatile("{\n\t.reg .pred P;\n"
                 "W%=:\n\t"
                 "mbarrier.try_wait.parity.acquire.cta.shared::cta.b64 P, [%0], %1, 0x989680;\n\t"
                 "@P bra D%=;\n\t"
                 "bra W%=;\n"
                 "D%=:\n\t}"
                 :: "r"(mb), "r"(parity) : "memory");
}
__device__ __forceinline__ void bulk_g2s(uint32_t dst, const void* src,
                                         uint32_t bytes, uint32_t mb) {
    asm volatile("cp.async.bulk.shared::cta.global.mbarrier::complete_tx::bytes "
                 "[%0], [%1], %2, [%3];"
                 :: "r"(dst), "l"(src), "r"(bytes), "r"(mb) : "memory");
}
__device__ __forceinline__ void ldsm_x4(uint32_t& r0, uint32_t& r1,
                                        uint32_t& r2, uint32_t& r3, uint32_t a) {
    asm volatile("ldmatrix.sync.aligned.m8n8.x4.shared.b16 {%0,%1,%2,%3}, [%4];"
                 : "=r"(r0), "=r"(r1), "=r"(r2), "=r"(r3) : "r"(a));
}
__device__ __forceinline__ void mma_bf16(float& c0, float& c1, float& c2, float& c3,
                                         uint32_t a0, uint32_t a1, uint32_t a2, uint32_t a3,
                                         uint32_t b0, uint32_t b1) {
    asm volatile("mma.sync.aligned.m16n8k16.row.col.f32.bf16.bf16.f32 "
                 "{%0,%1,%2,%3},{%4,%5,%6,%7},{%8,%9},{%0,%1,%2,%3};"
                 : "+f"(c0), "+f"(c1), "+f"(c2), "+f"(c3)
                 : "r"(a0), "r"(a1), "r"(a2), "r"(a3), "r"(b0), "r"(b1));
}

// ---------------------------------------------------------------------------
// Vectorized merged packing kernel (+ folded flag reset in block 0)
// ---------------------------------------------------------------------------
#define PX_G  ((size_t)E1_NC * B_ROWS * 5)
#define PW_G  ((size_t)M_EXP * E1_NC * 128 * 5)
#define P2E_G ((size_t)M_EXP * 4 * 96 * 5)
#define P2T_G ((size_t)N_TASK * 4 * 96 * 5)
#define PACK_G_TOTAL (PX_G + PW_G + P2E_G + P2T_G)

__device__ __forceinline__ uint32_t bf2u(float a, float b) {
    __nv_bfloat162 t;
    t.x = __float2bfloat16(a);
    t.y = __float2bfloat16(b);
    return *reinterpret_cast<uint32_t*>(&t);
}

__device__ __forceinline__ void split8_store(const float* f,
                                             __nv_bfloat16* __restrict__ ph,
                                             __nv_bfloat16* __restrict__ pl,
                                             size_t g8)
{
    float l[8];
    #pragma unroll
    for (int j = 0; j < 8; j++) {
        __nv_bfloat16 hb = __float2bfloat16(f[j]);
        l[j] = f[j] - __bfloat162float(hb);
    }
    uint4 H, L;
    H.x = bf2u(f[0] - l[0], f[1] - l[1]);
    H.y = bf2u(f[2] - l[2], f[3] - l[3]);
    H.z = bf2u(f[4] - l[4], f[5] - l[5]);
    H.w = bf2u(f[6] - l[6], f[7] - l[7]);
    L.x = bf2u(l[0], l[1]);
    L.y = bf2u(l[2], l[3]);
    L.z = bf2u(l[4], l[5]);
    L.w = bf2u(l[6], l[7]);
    *reinterpret_cast<uint4*>(ph + g8 * 8) = H;
    *reinterpret_cast<uint4*>(pl + g8 * 8) = L;
}

__global__ void pack_all_kernel(const float* __restrict__ x,
                                const float* __restrict__ eW1,
                                const float* __restrict__ eW2,
                                const float* __restrict__ tW2,
                                __nv_bfloat16* __restrict__ xph,
                                __nv_bfloat16* __restrict__ xpl,
                                __nv_bfloat16* __restrict__ wph,
                                __nv_bfloat16* __restrict__ wpl,
                                __nv_bfloat16* __restrict__ w2h,
                                __nv_bfloat16* __restrict__ w2l,
                                __nv_bfloat16* __restrict__ tw2h,
                                __nv_bfloat16* __restrict__ tw2l)
{
    if (blockIdx.x == 0 && threadIdx.x < NTILES)
        g_ready[threadIdx.x] = 0;

    size_t gi = (size_t)blockIdx.x * blockDim.x + threadIdx.x;
    if (gi >= PACK_G_TOTAL) return;

    float f[8];
    #pragma unroll
    for (int j = 0; j < 8; j++) f[j] = 0.f;

    if (gi < PX_G) {
        size_t i = gi;
        int g = (int)(i % 5);
        size_t rc = i / 5;
        int row = (int)(rc % B_ROWS);
        int c   = (int)(rc / B_ROWS);
        if (g < 4) {
            const float* src = x + (size_t)row * K_IN + c * E1_BK + g * 8;
            float4 a = *reinterpret_cast<const float4*>(src);
            float4 b = *reinterpret_cast<const float4*>(src + 4);
            f[0] = a.x; f[1] = a.y; f[2] = a.z; f[3] = a.w;
            f[4] = b.x; f[5] = b.y; f[6] = b.z; f[7] = b.w;
        }
        split8_store(f, xph, xpl, i);
    } else if (gi < PX_G + PW_G) {
        size_t i = gi - PX_G;
        int g = (int)(i % 5);
        int n = (int)((i / 5) % 128);
        int c = (int)((i / (5 * 128)) % E1_NC);
        int m = (int)(i / ((size_t)5 * 128 * E1_NC));
        if (g < 4 && n < H1_DIM) {
            #pragma unroll
            for (int j = 0; j < 8; j++) {
                int k = c * E1_BK + g * 8 + j;
                f[j] = eW1[((size_t)m * K_IN + k) * H1_DIM + n];
            }
        }
        split8_store(f, wph, wpl, i);
    } else if (gi < PX_G + PW_G + P2E_G) {
        size_t i = gi - PX_G - PW_G;
        int g = (int)(i % 5);
        int n = (int)((i / 5) % 96);
        int c = (int)((i / (5 * 96)) % 4);
        int b = (int)(i / ((size_t)5 * 96 * 4));
        if (g < 4 && n < 84) {
            #pragma unroll
            for (int j = 0; j < 8; j++) {
                int k = c * 32 + g * 8 + j;
                if (k < 120) f[j] = eW2[((size_t)b * 120 + k) * 84 + n];
            }
        }
        split8_store(f, w2h, w2l, i);
    } else {
        size_t i = gi - PX_G - PW_G - P2E_G;
        int g = (int)(i % 5);
        int n = (int)((i / 5) % 96);
        int c = (int)((i / (5 * 96)) % 4);
        int b = (int)(i / ((size_t)5 * 96 * 4));
        if (g < 4 && n < 84) {
            #pragma unroll
            for (int j = 0; j < 8; j++) {
                int k = c * 32 + g * 8 + j;
                if (k < 120) f[j] = tW2[((size_t)b * 120 + k) * 84 + n];
            }
        }
        split8_store(f, tw2h, tw2l, i);
    }
}

// ---------------------------------------------------------------------------
// fused kernel: blocks [0,640) = expert; [640, 7040) = task (flag-synced).
// MMA inner blocks are PASS-MAJOR: all HH, then all HL, then all LH —
// consecutive MMAs hit different accumulators (16 independent chains).
// Per-accumulator pass order unchanged (HH,HL,LH) -> bit-identical output.
// smem 110,592 B -> 2 CTAs/SM.  256 threads.
// ---------------------------------------------------------------------------
#define RS          80
#define STG_SZ      40960
#define XA_H        0
#define XA_L        10240
#define XB_H        20480
#define XB_L        30720
#define EB_H        81920
#define EB_L        89600
#define EW3S        97280
#define EMB         100640
#define MSTR        90

#define TK_AH      0
#define TK_AL      40960
#define TB_H       81920
#define TB_L       89600
#define TK_GS      97280
#define TK_W1      102400
#define TK_W3      107200
#define TK_MB      110560
#define FK_SMEM    110592

__global__ __launch_bounds__(256, 2)
void fused_kernel(const __nv_bfloat16* __restrict__ xph,
                  const __nv_bfloat16* __restrict__ xpl,
                  const __nv_bfloat16* __restrict__ wph,
                  const __nv_bfloat16* __restrict__ wpl,
                  const float* __restrict__ eb1,
                  const __nv_bfloat16* __restrict__ w2h,
                  const __nv_bfloat16* __restrict__ w2l,
                  const float* __restrict__ eb2,
                  const float* __restrict__ eW3,
                  const float* __restrict__ eb3,
                  const float* __restrict__ gw,
                  const int*   __restrict__ gm,
                  const float* __restrict__ tW1,
                  const float* __restrict__ tb1,
                  const __nv_bfloat16* __restrict__ tw2h,
                  const __nv_bfloat16* __restrict__ tw2l,
                  const float* __restrict__ tb2,
                  const float* __restrict__ tW3,
                  const float* __restrict__ tb3,
                  const float* __restrict__ gl,
                  float* __restrict__ EO,
                  float* __restrict__ Out,
                  float* __restrict__ Loss)
{
    extern __shared__ char smem[];
    const uint32_t sb = smem_u32(smem);
    const int t    = threadIdx.x;
    const int lane = t & 31;
    const int wid  = t >> 5;
    const int wm   = wid >> 1;
    const int wn   = wid & 1;
    const int bx   = blockIdx.x;

    if (bx < M_EXP * NTILES) {
        // =================== EXPERT ROLE ===================
        const int m     = bx % M_EXP;
        const int tileY = bx / M_EXP;
        const int r0    = tileY * 128;

        const uint32_t mb = sb + EMB;

        if (t == 0) {
            mbar_init(mb + 0, 1);
            mbar_init(mb + 8, 1);
            mbar_init(mb + 16, 1);
        }
        __syncthreads();

        auto issue_e1 = [&](int c, int s) {
            mbar_expect_tx(mb + 8 * s, 4 * 10240);
            const uint32_t stg = sb + s * STG_SZ;
            const size_t aoff = ((size_t)c * B_ROWS + (size_t)tileY * 128) * PK_COLS;
            const size_t boff = ((size_t)m * E1_NC + c) * 128 * PK_COLS;
            bulk_g2s(stg + XA_H, xph + aoff, 10240, mb + 8 * s);
            bulk_g2s(stg + XA_L, xpl + aoff, 10240, mb + 8 * s);
            bulk_g2s(stg + XB_H, wph + boff, 10240, mb + 8 * s);
            bulk_g2s(stg + XB_L, wpl + boff, 10240, mb + 8 * s);
        };

        if (t == 0) {
            mbar_expect_tx(mb + 16, 2 * 7680);
            bulk_g2s(sb + EB_H, w2h + (size_t)m * 4 * 3840, 7680, mb + 16);
            bulk_g2s(sb + EB_L, w2l + (size_t)m * 4 * 3840, 7680, mb + 16);
            issue_e1(0, 0);
        }

        // -------- E1 --------
        float acc[2][8][4];
        #pragma unroll
        for (int i = 0; i < 2; i++)
            #pragma unroll
            for (int j = 0; j < 8; j++)
                #pragma unroll
                for (int q = 0; q < 4; q++)
                    acc[i][j][q] = 0.f;

        const uint32_t a_base = (uint32_t)((wm * 32 + (lane & 15)) * RS + (lane >> 4) * 16);
        const uint32_t b_base = (uint32_t)((wn * 64 + (lane & 15)) * RS + (lane >> 4) * 16);

        uint32_t ph[2] = {0u, 0u};

        for (int c = 0; c < E1_NC; c++) {
            const int s = c & 1;
            if (c + 1 < E1_NC && t == 0) issue_e1(c + 1, s ^ 1);
            mbar_wait(mb + 8 * s, ph[s]);
            ph[s] ^= 1u;

            const uint32_t stg = sb + s * STG_SZ;
            #pragma unroll
            for (int ks = 0; ks < 2; ks++) {
                const uint32_t ko = ks * 32;
                uint32_t ah[2][4], al[2][4];
                #pragma unroll
                for (int mt = 0; mt < 2; mt++) {
                    uint32_t ad = stg + a_base + mt * (16 * RS) + ko;
                    ldsm_x4(ah[mt][0], ah[mt][1], ah[mt][2], ah[mt][3], ad + XA_H);
                    ldsm_x4(al[mt][0], al[mt][1], al[mt][2], al[mt][3], ad + XA_L);
                }
                uint32_t bh[4][4], bl[4][4];
                #pragma unroll
                for (int g = 0; g < 4; g++) {
                    uint32_t bd = stg + b_base + g * (16 * RS) + ko;
                    ldsm_x4(bh[g][0], bh[g][1], bh[g][2], bh[g][3], bd + XB_H);
                    ldsm_x4(bl[g][0], bl[g][1], bl[g][2], bl[g][3], bd + XB_L);
                }
                // pass-major: HH for all acc, then HL, then LH
                #pragma unroll
                for (int mt = 0; mt < 2; mt++)
                    #pragma unroll
                    for (int nt = 0; nt < 8; nt++) {
                        const int g = nt >> 1, p = (nt & 1);
                        float* cc = acc[mt][nt];
                        mma_bf16(cc[0], cc[1], cc[2], cc[3],
                                 ah[mt][0], ah[mt][1], ah[mt][2], ah[mt][3],
                                 bh[g][p], bh[g][p + 2]);
                    }
                #pragma unroll
                for (int mt = 0; mt < 2; mt++)
                    #pragma unroll
                    for (int nt = 0; nt < 8; nt++) {
                        const int g = nt >> 1, p = (nt & 1);
                        float* cc = acc[mt][nt];
                        mma_bf16(cc[0], cc[1], cc[2], cc[3],
                                 ah[mt][0], ah[mt][1], ah[mt][2], ah[mt][3],
                                 bl[g][p], bl[g][p + 2]);
                    }
                #pragma unroll
                for (int mt = 0; mt < 2; mt++)
                    #pragma unroll
                    for (int nt = 0; nt < 8; nt++) {
                        const int g = nt >> 1, p = (nt & 1);
                        float* cc = acc[mt][nt];
                        mma_bf16(cc[0], cc[1], cc[2], cc[3],
                                 al[mt][0], al[mt][1], al[mt][2], al[mt][3],
                                 bh[g][p], bh[g][p + 2]);
                    }
            }
            __syncthreads();
        }

        // -------- H1 tile -> smem (relu+bias, split hi/lo) --------
        {
            const float* bias = eb1 + (size_t)m * H1_DIM;
            const int rl = wm * 32 + (lane >> 2);
            const int cb = wn * 64 + (lane & 3) * 2;
            #pragma unroll
            for (int mt = 0; mt < 2; mt++) {
                #pragma unroll
                for (int half = 0; half < 2; half++) {
                    const int r = rl + mt * 16 + half * 8;
                    #pragma unroll
                    for (int nt = 0; nt < 8; nt++) {
                        const int ccol = cb + nt * 8;
                        if (ccol < H1_DIM) {
                            float v0 = fmaxf(acc[mt][nt][half * 2 + 0] + bias[ccol], 0.f);
                            float v1 = fmaxf(acc[mt][nt][half * 2 + 1] + bias[ccol + 1], 0.f);
                            __nv_bfloat16 h0 = __float2bfloat16(v0);
                            __nv_bfloat16 h1 = __float2bfloat16(v1);
                            __nv_bfloat162 hh; hh.x = h0; hh.y = h1;
                            __nv_bfloat162 ll;
                            ll.x = __float2bfloat16(v0 - __bfloat162float(h0));
                            ll.y = __float2bfloat16(v1 - __bfloat162float(h1));
                            uint32_t off = (ccol >> 5) * 10240 + r * RS + (ccol & 31) * 2;
                            *reinterpret_cast<__nv_bfloat162*>(smem + 0     + off) = hh;
                            *reinterpret_cast<__nv_bfloat162*>(smem + 40960 + off) = ll;
                        }
                    }
                }
            }
            if (t < 128) {
                uint32_t off = 3 * 10240 + t * RS + 48;
                *reinterpret_cast<uint4*>(smem + 0     + off) = make_uint4(0u,0u,0u,0u);
                *reinterpret_cast<uint4*>(smem + 40960 + off) = make_uint4(0u,0u,0u,0u);
            }
            float* w3s = reinterpret_cast<float*>(smem + EW3S);
            const float* w3g = eW3 + (size_t)m * (84 * T_OUT);
            for (int i = t; i < 84 * T_OUT; i += 256) w3s[i] = w3g[i];
        }
        __syncthreads();

        // -------- E2 MMA (B streamed per chunk; pass-major) --------
        float acc2[2][6][4];
        #pragma unroll
        for (int i = 0; i < 2; i++)
            #pragma unroll
            for (int j = 0; j < 6; j++)
                #pragma unroll
                for (int q = 0; q < 4; q++)
                    acc2[i][j][q] = 0.f;

        const uint32_t b2_base = (uint32_t)((wn * 48 + (lane & 15)) * RS + (lane >> 4) * 16);
        uint32_t phb = 0u;
        #pragma unroll
        for (int ch = 0; ch < 4; ch++) {
            mbar_wait(mb + 16, phb);
            phb ^= 1u;
            #pragma unroll
            for (int ks = 0; ks < 2; ks++) {
                const uint32_t ko = ks * 32;
                uint32_t ah[2][4], al[2][4];
                #pragma unroll
                for (int mt = 0; mt < 2; mt++) {
                    uint32_t ad = sb + ch * 10240 + a_base + mt * (16 * RS) + ko;
                    ldsm_x4(ah[mt][0], ah[mt][1], ah[mt][2], ah[mt][3], ad + 0);
                    ldsm_x4(al[mt][0], al[mt][1], al[mt][2], al[mt][3], ad + 40960);
                }
                uint32_t bh[3][4], bl[3][4];
                #pragma unroll
                for (int g = 0; g < 3; g++) {
                    uint32_t bd = sb + b2_base + g * (16 * RS) + ko;
                    ldsm_x4(bh[g][0], bh[g][1], bh[g][2], bh[g][3], bd + EB_H);
                    ldsm_x4(bl[g][0], bl[g][1], bl[g][2], bl[g][3], bd + EB_L);
                }
                #pragma unroll
                for (int mt = 0; mt < 2; mt++)
                    #pragma unroll
                    for (int nt = 0; nt < 6; nt++) {
                        const int g = nt >> 1, p = (nt & 1);
                        float* cc = acc2[mt][nt];
                        mma_bf16(cc[0], cc[1], cc[2], cc[3],
                                 ah[mt][0], ah[mt][1], ah[mt][2], ah[mt][3],
                                 bh[g][p], bh[g][p + 2]);
                    }
                #pragma unroll
                for (int mt = 0; mt < 2; mt++)
                    #pragma unroll
                    for (int nt = 0; nt < 6; nt++) {
                        const int g = nt >> 1, p = (nt & 1);
                        float* cc = acc2[mt][nt];
                        mma_bf16(cc[0], cc[1], cc[2], cc[3],
                                 ah[mt][0], ah[mt][1], ah[mt][2], ah[mt][3],
                                 bl[g][p], bl[g][p + 2]);
                    }
                #pragma unroll
                for (int mt = 0; mt < 2; mt++)
                    #pragma unroll
                    for (int nt = 0; nt < 6; nt++) {
                        const int g = nt >> 1, p = (nt & 1);
                        float* cc = acc2[mt][nt];
                        mma_bf16(cc[0], cc[1], cc[2], cc[3],
                                 al[mt][0], al[mt][1], al[mt][2], al[mt][3],
                                 bh[g][p], bh[g][p + 2]);
                    }
            }
            __syncthreads();
            if (ch < 3 && t == 0) {
                mbar_expect_tx(mb + 16, 2 * 7680);
                bulk_g2s(sb + EB_H, w2h + ((size_t)m * 4 + ch + 1) * 3840, 7680, mb + 16);
                bulk_g2s(sb + EB_L, w2l + ((size_t)m * 4 + ch + 1) * 3840, 7680, mb + 16);
            }
        }

        // -------- E3 epilogue --------
        float* mids = reinterpret_cast<float*>(smem);
        float* w3s  = reinterpret_cast<float*>(smem + EW3S);
        {
            const float* b2 = eb2 + (size_t)m * 84;
            const int rl = wm * 32 + (lane >> 2);
            const int cb = wn * 48 + (lane & 3) * 2;
            #pragma unroll
            for (int mt = 0; mt < 2; mt++) {
                #pragma unroll
                for (int half = 0; half < 2; half++) {
                    const int r = rl + mt * 16 + half * 8;
                    float* row = mids + r * MSTR;
                    #pragma unroll
                    for (int nt = 0; nt < 6; nt++) {
                        const int ccol = cb + nt * 8;
                        if (ccol < 84) {
                            float2 v;
                            v.x = fmaxf(acc2[mt][nt][half * 2 + 0] + b2[ccol], 0.f);
                            v.y = fmaxf(acc2[mt][nt][half * 2 + 1] + b2[ccol + 1], 0.f);
                            *reinterpret_cast<float2*>(row + ccol) = v;
                        }
                    }
                }
            }
        }
        __syncthreads();
        {
            const int r  = t >> 1;
            const int c0 = (t & 1) * 5;
            const float* b3 = eb3 + (size_t)m * T_OUT;
            float a[5];
            #pragma unroll
            for (int j = 0; j < 5; j++) a[j] = b3[c0 + j];
            const float* row = mids + r * MSTR;
            for (int k = 0; k < 84; k++) {
                float tv = row[k];
                #pragma unroll
                for (int j = 0; j < 5; j++)
                    a[j] = fmaf(tv, w3s[k * T_OUT + c0 + j], a[j]);
            }
            float* dst = EO + ((size_t)m * B_ROWS + r0 + r) * T_OUT + c0;
            #pragma unroll
            for (int j = 0; j < 5; j++) dst[j] = a[j];
        }
        __syncthreads();
        if (t == 0) {
            __threadfence();
            atomicAdd(&g_ready[tileY], 1);
        }
    } else {
        // =================== TASK ROLE ===================
        const int j2    = bx - M_EXP * NTILES;
        const int tileY = j2 / N_TASK;
        const int n     = j2 % N_TASK;
        const int r0    = tileY * 128;

        const uint32_t mb = sb + TK_MB;
        if (t == 0) mbar_init(mb, 1);
        __syncthreads();
        if (t == 0) {
            mbar_expect_tx(mb, 2 * 7680);
            bulk_g2s(sb + TB_H, tw2h + (size_t)n * 4 * 3840, 7680, mb);
            bulk_g2s(sb + TB_L, tw2l + (size_t)n * 4 * 3840, 7680, mb);
        }

        if (tileY == 0 && t == 32) {
            float acc = 0.f;
            #pragma unroll
            for (int m = 0; m < M_EXP; m++) {
                float v = gl[m * N_TASK + n];
                float ls = (v > 0.f) ? (-log1pf(expf(-v))) : (v - log1pf(expf(v)));
                acc += ls;
            }
            Loss[n] = acc;
        }

        float* Gs  = reinterpret_cast<float*>(smem + TK_GS);
        float* W1s = reinterpret_cast<float*>(smem + TK_W1);
        float* w3s = reinterpret_cast<float*>(smem + TK_W3);

        for (int i = t; i < F_CONN * 120; i += 256)
            W1s[i] = tW1[(size_t)n * F_CONN * 120 + i];
        for (int i = t; i < 84 * T_OUT; i += 256)
            w3s[i] = tW3[(size_t)n * 84 * T_OUT + i];

        if (t == 0) {
            while (atomicAdd(&g_ready[tileY], 0) < M_EXP) __nanosleep(64);
        }
        __syncthreads();

        float w[M_EXP];
        #pragma unroll
        for (int m = 0; m < M_EXP; m++)
            w[m] = gw[m * N_TASK + n] * (float)gm[m * N_TASK + n];

        for (int i = t; i < 128 * F_CONN; i += 256) {
            float acc = 0.f;
            #pragma unroll
            for (int m = 0; m < M_EXP; m++)
                acc = fmaf(w[m], __ldcg(&EO[((size_t)m * B_ROWS + r0) * F_CONN + i]), acc);
            Gs[i] = acc;
        }
        __syncthreads();

        // T1
        {
            const int r  = t >> 1;
            const int h0 = (t & 1) * 60;
            float g[F_CONN];
            #pragma unroll
            for (int f = 0; f < F_CONN; f++) g[f] = Gs[r * F_CONN + f];

            unsigned long long a2[30];
            const float* b1 = tb1 + (size_t)n * 120 + h0;
            #pragma unroll
            for (int j = 0; j < 30; j++) a2[j] = pack2(b1[2 * j], b1[2 * j + 1]);
            #pragma unroll
            for (int f = 0; f < F_CONN; f++) {
                unsigned long long gv = dup2(g[f]);
                const unsigned long long* wrow =
                    reinterpret_cast<const unsigned long long*>(W1s + f * 120 + h0);
                #pragma unroll
                for (int j = 0; j < 30; j++) fma2(a2[j], gv, wrow[j]);
            }
            #pragma unroll
            for (int j = 0; j < 30; j++) {
                float v0, v1;
                unpack2(a2[j], v0, v1);
                v0 = fmaxf(v0, 0.f);
                v1 = fmaxf(v1, 0.f);
                __nv_bfloat16 h0b = __float2bfloat16(v0);
                __nv_bfloat16 h1b = __float2bfloat16(v1);
                __nv_bfloat162 hh; hh.x = h0b; hh.y = h1b;
                __nv_bfloat162 ll;
                ll.x = __float2bfloat16(v0 - __bfloat162float(h0b));
                ll.y = __float2bfloat16(v1 - __bfloat162float(h1b));
                const int c = h0 + 2 * j;
                uint32_t off = (c >> 5) * 10240 + r * RS + (c & 31) * 2;
                *reinterpret_cast<__nv_bfloat162*>(smem + TK_AH + off) = hh;
                *reinterpret_cast<__nv_bfloat162*>(smem + TK_AL + off) = ll;
            }
            if (t & 1) {
                uint32_t off = 3 * 10240 + r * RS + 48;
                *reinterpret_cast<uint4*>(smem + TK_AH + off) = make_uint4(0u,0u,0u,0u);
                *reinterpret_cast<uint4*>(smem + TK_AL + off) = make_uint4(0u,0u,0u,0u);
            }
        }
        __syncthreads();

        // T2 MMA (B streamed per chunk; pass-major)
        float acc2[2][6][4];
        #pragma unroll
        for (int i = 0; i < 2; i++)
            #pragma unroll
            for (int j = 0; j < 6; j++)
                #pragma unroll
                for (int q = 0; q < 4; q++)
                    acc2[i][j][q] = 0.f;

        const uint32_t a_base  = (uint32_t)((wm * 32 + (lane & 15)) * RS + (lane >> 4) * 16);
        const uint32_t b2_base = (uint32_t)((wn * 48 + (lane & 15)) * RS + (lane >> 4) * 16);
        uint32_t phb = 0u;
        #pragma unroll
        for (int ch = 0; ch < 4; ch++) {
            mbar_wait(mb, phb);
            phb ^= 1u;
            #pragma unroll
            for (int ks = 0; ks < 2; ks++) {
                const uint32_t ko = ks * 32;
                uint32_t ah[2][4], al[2][4];
                #pragma unroll
                for (int mt = 0; mt < 2; mt++) {
                    uint32_t ad = sb + ch * 10240 + a_base + mt * (16 * RS) + ko;
                    ldsm_x4(ah[mt][0], ah[mt][1], ah[mt][2], ah[mt][3], ad + TK_AH);
                    ldsm_x4(al[mt][0], al[mt][1], al[mt][2], al[mt][3], ad + TK_AL);
                }
                uint32_t bh[3][4], bl[3][4];
                #pragma unroll
                for (int g = 0; g < 3; g++) {
                    uint32_t bd = sb + b2_base + g * (16 * RS) + ko;
                    ldsm_x4(bh[g][0], bh[g][1], bh[g][2], bh[g][3], bd + TB_H);
                    ldsm_x4(bl[g][0], bl[g][1], bl[g][2], bl[g][3], bd + TB_L);
                }
                #pragma unroll
                for (int mt = 0; mt < 2; mt++)
                    #pragma unroll
                    for (int nt = 0; nt < 6; nt++) {
                        const int g = nt >> 1, p = (nt & 1);
                        float* cc = acc2[mt][nt];
                        mma_bf16(cc[0], cc[1], cc[2], cc[3],
                                 ah[mt][0], ah[mt][1], ah[mt][2], ah[mt][3],
                                 bh[g][p], bh[g][p + 2]);
                    }
                #pragma unroll
                for (int mt = 0; mt < 2; mt++)
                    #pragma unroll
                    for (int nt = 0; nt < 6; nt++) {
                        const int g = nt >> 1, p = (nt & 1);
                        float* cc = acc2[mt][nt];
                        mma_bf16(cc[0], cc[1], cc[2], cc[3],
                                 ah[mt][0], ah[mt][1], ah[mt][2], ah[mt][3],
                                 bl[g][p], bl[g][p + 2]);
                    }
                #pragma unroll
                for (int mt = 0; mt < 2; mt++)
                    #pragma unroll
                    for (int nt = 0; nt < 6; nt++) {
                        const int g = nt >> 1, p = (nt & 1);
                        float* cc = acc2[mt][nt];
                        mma_bf16(cc[0], cc[1], cc[2], cc[3],
                                 al[mt][0], al[mt][1], al[mt][2], al[mt][3],
                                 bh[g][p], bh[g][p + 2]);
                    }
            }
            __syncthreads();
            if (ch < 3 && t == 0) {
                mbar_expect_tx(mb, 2 * 7680);
                bulk_g2s(sb + TB_H, tw2h + ((size_t)n * 4 + ch + 1) * 3840, 7680, mb);
                bulk_g2s(sb + TB_L, tw2l + ((size_t)n * 4 + ch + 1) * 3840, 7680, mb);
            }
        }

        // T3 epilogue
        float* mids = reinterpret_cast<float*>(smem);
        {
            const float* b2 = tb2 + (size_t)n * 84;
            const int rl = wm * 32 + (lane >> 2);
            const int cb = wn * 48 + (lane & 3) * 2;
            #pragma unroll
            for (int mt = 0; mt < 2; mt++) {
                #pragma unroll
                for (int half = 0; half < 2; half++) {
                    const int r = rl + mt * 16 + half * 8;
                    float* row = mids + r * MSTR;
                    #pragma unroll
                    for (int nt = 0; nt < 6; nt++) {
                        const int ccol = cb + nt * 8;
                        if (ccol < 84) {
                            float2 v;
                            v.x = fmaxf(acc2[mt][nt][half * 2 + 0] + b2[ccol], 0.f);
                            v.y = fmaxf(acc2[mt][nt][half * 2 + 1] + b2[ccol + 1], 0.f);
                            *reinterpret_cast<float2*>(row + ccol) = v;
                        }
                    }
                }
            }
        }
        __syncthreads();
        {
            const int r  = t >> 1;
            const int c0 = (t & 1) * 5;
            const float* b3 = tb3 + (size_t)n * T_OUT;
            float a[5];
            #pragma unroll
            for (int j = 0; j < 5; j++) a[j] = b3[c0 + j];
            const float* row = mids + r * MSTR;
            for (int k = 0; k < 84; k++) {
                float tv = row[k];
                #pragma unroll
                for (int j = 0; j < 5; j++)
                    a[j] = fmaf(tv, w3s[k * T_OUT + c0 + j], a[j]);
            }
            float* dst = Out + ((size_t)n * B_ROWS + r0 + r) * T_OUT + c0;
            #pragma unroll
            for (int j = 0; j < 5; j++) dst[j] = a[j];
        }
    }
}

// ---------------------------------------------------------------------------
// kernel_launch
// ---------------------------------------------------------------------------
extern "C" void kernel_launch(void* const* d_in, const int* in_sizes, int n_in,
                              void* d_out, int out_size)
{
    const float* x   = (const float*)d_in[0];
    const float* eW1 = (const float*)d_in[2];
    const float* eb1 = (const float*)d_in[3];
    const float* eW2 = (const float*)d_in[4];
    const float* eb2 = (const float*)d_in[5];
    const float* eW3 = (const float*)d_in[6];
    const float* eb3 = (const float*)d_in[7];
    const float* gw  = (const float*)d_in[8];
    const float* gl  = (const float*)d_in[9];
    const int*   gm  = (const int*)  d_in[10];
    const float* tW1 = (const float*)d_in[11];
    const float* tb1 = (const float*)d_in[12];
    const float* tW2 = (const float*)d_in[13];
    const float* tb2 = (const float*)d_in[14];
    const float* tW3 = (const float*)d_in[15];
    const float* tb3 = (const float*)d_in[16];
    float* out = (float*)d_out;

    float *EO;
    __nv_bfloat16 *xph, *xpl, *wph, *wpl, *w2h, *w2l, *tw2h, *tw2l;
    cudaGetSymbolAddress((void**)&EO,  g_EO);
    cudaGetSymbolAddress((void**)&xph, g_xph);
    cudaGetSymbolAddress((void**)&xpl, g_xpl);
    cudaGetSymbolAddress((void**)&wph, g_wph);
    cudaGetSymbolAddress((void**)&wpl, g_wpl);
    cudaGetSymbolAddress((void**)&w2h, g_w2h);
    cudaGetSymbolAddress((void**)&w2l, g_w2l);
    cudaGetSymbolAddress((void**)&tw2h, g_tw2h);
    cudaGetSymbolAddress((void**)&tw2l, g_tw2l);

    cudaFuncSetAttribute(fused_kernel,
                         cudaFuncAttributeMaxDynamicSharedMemorySize, FK_SMEM);

    // vectorized merged packing (one launch; also resets ready flags)
    {
        unsigned blocks = (unsigned)((PACK_G_TOTAL + 255) / 256);
        pack_all_kernel<<<blocks, 256>>>(x, eW1, eW2, tW2,
                                         xph, xpl, wph, wpl,
                                         w2h, w2l, tw2h, tw2l);
    }

    // fused expert+task with flag-based cross-phase overlap
    fused_kernel<<<(M_EXP + N_TASK) * NTILES, 256, FK_SMEM>>>(
        xph, xpl, wph, wpl, eb1, w2h, w2l, eb2, eW3, eb3,
        gw, gm, tW1, tb1, tw2h, tw2l, tb2, tW3, tb3, gl,
        EO, out, out + (long long)N_TASK * B_ROWS * T_OUT);
}